// round 1
// baseline (speedup 1.0000x reference)
#include <cuda_runtime.h>
#include <cuda_bf16.h>
#include <mma.h>

using namespace nvcuda;

// ---- problem constants ----
#define BD   2
#define DD   5
#define HH   32
#define WW   32
#define CC   256
#define NHH  8
#define NLL  5
#define NPP  16
#define HDD  32
#define MLPH 1024
#define HWW  1024
#define LQQ  5120
#define MM   10240     // B * LQ tokens

// ---- scratch (device globals; no runtime allocation allowed) ----
__device__ __align__(256) __nv_bfloat16 g_q[MM * CC];
__device__ __align__(256) __nv_bfloat16 g_hln[MM * CC];
__device__ __align__(256) __nv_bfloat16 g_samp[MM * CC];
__device__ __align__(256) __nv_bfloat16 g_mh[MM * MLPH];
__device__ __align__(256) __nv_bfloat16 g_vperm[BD * NHH * NLL * HWW * HDD];
__device__ __align__(256) float g_val[MM * CC];
__device__ __align__(256) float g_off[MM * 1280];
__device__ __align__(256) float g_aw[MM * 640];
__device__ __align__(256) float g_x1[MM * CC];
__device__ __align__(256) __nv_bfloat16 g_w_val[CC * CC];
__device__ __align__(256) __nv_bfloat16 g_w_off[CC * 1280];
__device__ __align__(256) __nv_bfloat16 g_w_attn[CC * 640];
__device__ __align__(256) __nv_bfloat16 g_w_out[CC * CC];
__device__ __align__(256) __nv_bfloat16 g_w_fc1[CC * MLPH];
__device__ __align__(256) __nv_bfloat16 g_w_fc2[MLPH * CC];

// =====================================================================
// weight conversion f32 -> bf16 (all six weight matrices in one kernel)
// =====================================================================
__global__ void convert_weights_kernel(const float* __restrict__ wv,
                                       const float* __restrict__ wo,
                                       const float* __restrict__ wa,
                                       const float* __restrict__ wout,
                                       const float* __restrict__ wf1,
                                       const float* __restrict__ wf2) {
    int i = blockIdx.x * 256 + threadIdx.x;
    // sizes: 65536, 327680, 163840, 65536, 262144, 262144  (sum 1,146,880)
    if (i < 65536) { g_w_val[i] = __float2bfloat16(wv[i]); return; }
    i -= 65536;
    if (i < 327680) { g_w_off[i] = __float2bfloat16(wo[i]); return; }
    i -= 327680;
    if (i < 163840) { g_w_attn[i] = __float2bfloat16(wa[i]); return; }
    i -= 163840;
    if (i < 65536) { g_w_out[i] = __float2bfloat16(wout[i]); return; }
    i -= 65536;
    if (i < 262144) { g_w_fc1[i] = __float2bfloat16(wf1[i]); return; }
    i -= 262144;
    if (i < 262144) { g_w_fc2[i] = __float2bfloat16(wf2[i]); }
}

// =====================================================================
// LayerNorm over C=256, one warp per row, bf16 output
// =====================================================================
__global__ void ln_kernel(const float* __restrict__ x,
                          const float* __restrict__ gam,
                          const float* __restrict__ bet,
                          __nv_bfloat16* __restrict__ out) {
    int warp = threadIdx.x >> 5, lane = threadIdx.x & 31;
    int row = blockIdx.x * 8 + warp;
    const float4* xp = (const float4*)(x + (size_t)row * CC);
    float4 a = xp[lane * 2];
    float4 b = xp[lane * 2 + 1];
    float s  = a.x + a.y + a.z + a.w + b.x + b.y + b.z + b.w;
    float sq = a.x*a.x + a.y*a.y + a.z*a.z + a.w*a.w
             + b.x*b.x + b.y*b.y + b.z*b.z + b.w*b.w;
#pragma unroll
    for (int o = 16; o > 0; o >>= 1) {
        s  += __shfl_xor_sync(0xffffffffu, s,  o);
        sq += __shfl_xor_sync(0xffffffffu, sq, o);
    }
    float mean = s * (1.0f / CC);
    float var  = sq * (1.0f / CC) - mean * mean;
    float rs   = rsqrtf(var + 1e-5f);
    const float4* gp = (const float4*)gam;
    const float4* bp = (const float4*)bet;
    float4 g0 = gp[lane * 2], g1 = gp[lane * 2 + 1];
    float4 b0 = bp[lane * 2], b1 = bp[lane * 2 + 1];
    float o0 = (a.x - mean) * rs * g0.x + b0.x;
    float o1 = (a.y - mean) * rs * g0.y + b0.y;
    float o2 = (a.z - mean) * rs * g0.z + b0.z;
    float o3 = (a.w - mean) * rs * g0.w + b0.w;
    float o4 = (b.x - mean) * rs * g1.x + b1.x;
    float o5 = (b.y - mean) * rs * g1.y + b1.y;
    float o6 = (b.z - mean) * rs * g1.z + b1.z;
    float o7 = (b.w - mean) * rs * g1.w + b1.w;
    __nv_bfloat162 r0 = __floats2bfloat162_rn(o0, o1);
    __nv_bfloat162 r1 = __floats2bfloat162_rn(o2, o3);
    __nv_bfloat162 r2 = __floats2bfloat162_rn(o4, o5);
    __nv_bfloat162 r3 = __floats2bfloat162_rn(o6, o7);
    uint4 u;
    u.x = *(unsigned int*)&r0; u.y = *(unsigned int*)&r1;
    u.z = *(unsigned int*)&r2; u.w = *(unsigned int*)&r3;
    ((uint4*)(out + (size_t)row * CC))[lane] = u;
}

// =====================================================================
// bf16 WMMA GEMM  C[M,N] = A[M,K] @ B[K,N] + bias (+gelu) (+residual)
// tiles: block 128x64, 8 warps each 32x32, K-step 32
// =====================================================================
__global__ void gemm_bf16_kernel(const __nv_bfloat16* __restrict__ A,
                                 const __nv_bfloat16* __restrict__ Bw,
                                 const float* __restrict__ bias,
                                 const float* __restrict__ resid,
                                 float* __restrict__ out_f32,
                                 __nv_bfloat16* __restrict__ out_bf16,
                                 int M, int N, int K, int act) {
    __shared__ __align__(16) unsigned char smem_raw[34816];
    __nv_bfloat16* sa = (__nv_bfloat16*)smem_raw;                 // 128 x 40
    __nv_bfloat16* sb = (__nv_bfloat16*)(smem_raw + 128 * 40 * 2); // 32 x 72
    float* sc = (float*)smem_raw;                                  // 128 x 68

    int bm = blockIdx.y, bn = blockIdx.x;
    int tid = threadIdx.x;
    int w  = tid >> 5;
    int wm = w >> 1, wn = w & 1;

    wmma::fragment<wmma::accumulator, 16, 16, 16, float> cf[2][2];
#pragma unroll
    for (int i = 0; i < 2; ++i)
#pragma unroll
        for (int j = 0; j < 2; ++j)
            wmma::fill_fragment(cf[i][j], 0.0f);

    for (int k0 = 0; k0 < K; k0 += 32) {
        __syncthreads();
#pragma unroll
        for (int u0 = 0; u0 < 2; ++u0) {
            int u = tid + u0 * 256;
            int row = u >> 2, c8 = (u & 3) << 3;
            *(uint4*)(sa + row * 40 + c8) =
                *(const uint4*)(A + (size_t)(bm * 128 + row) * K + k0 + c8);
        }
        {
            int row = tid >> 3, c8 = (tid & 7) << 3;
            *(uint4*)(sb + row * 72 + c8) =
                *(const uint4*)(Bw + (size_t)(k0 + row) * N + bn * 64 + c8);
        }
        __syncthreads();
#pragma unroll
        for (int kk = 0; kk < 32; kk += 16) {
            wmma::fragment<wmma::matrix_a, 16, 16, 16, __nv_bfloat16, wmma::row_major> af[2];
            wmma::fragment<wmma::matrix_b, 16, 16, 16, __nv_bfloat16, wmma::row_major> bf[2];
#pragma unroll
            for (int i = 0; i < 2; ++i)
                wmma::load_matrix_sync(af[i], sa + (wm * 32 + i * 16) * 40 + kk, 40);
#pragma unroll
            for (int j = 0; j < 2; ++j)
                wmma::load_matrix_sync(bf[j], sb + kk * 72 + wn * 32 + j * 16, 72);
#pragma unroll
            for (int i = 0; i < 2; ++i)
#pragma unroll
                for (int j = 0; j < 2; ++j)
                    wmma::mma_sync(cf[i][j], af[i], bf[j], cf[i][j]);
        }
    }
    __syncthreads();
#pragma unroll
    for (int i = 0; i < 2; ++i)
#pragma unroll
        for (int j = 0; j < 2; ++j)
            wmma::store_matrix_sync(sc + (wm * 32 + i * 16) * 68 + wn * 32 + j * 16,
                                    cf[i][j], 68, wmma::mem_row_major);
    __syncthreads();

    for (int e = tid; e < 128 * 64; e += 256) {
        int row = e >> 6, col = e & 63;
        int gr = bm * 128 + row, gc = bn * 64 + col;
        float v = sc[row * 68 + col] + bias[gc];
        if (act) v = 0.5f * v * (1.0f + erff(v * 0.70710678118654752f));
        if (resid) v += resid[(size_t)gr * N + gc];
        if (out_f32) out_f32[(size_t)gr * N + gc] = v;
        if (out_bf16) out_bf16[(size_t)gr * N + gc] = __float2bfloat16(v);
    }
}

// =====================================================================
// permute val [b, l*HW+yx, h*32+d] (f32)  ->  vperm [b,h,l,yx,d] (bf16)
// =====================================================================
__global__ void permute_val_kernel() {
    int idx = blockIdx.x * 256 + threadIdx.x;        // 2,621,440 total
    int d  = idx & 31;
    int yx = (idx >> 5) & 1023;
    int l  = (idx >> 15) % NLL;
    int bh = idx / (NLL << 15);
    int h = bh & 7, b = bh >> 3;
    int token = b * LQQ + l * HWW + yx;
    g_vperm[idx] = __float2bfloat16(g_val[(size_t)token * CC + h * 32 + d]);
}

// =====================================================================
// softmax over 80 (per token,head), in place on g_aw; one warp per row
// =====================================================================
__global__ void softmax80_kernel() {
    int warp = threadIdx.x >> 5, lane = threadIdx.x & 31;
    int r = blockIdx.x * 8 + warp;                   // 81920 rows
    float* p = g_aw + (size_t)r * 80;
    float v0 = p[lane];
    float v1 = p[lane + 32];
    float v2 = (lane < 16) ? p[lane + 64] : -1e30f;
    float m = fmaxf(fmaxf(v0, v1), v2);
#pragma unroll
    for (int o = 16; o > 0; o >>= 1) m = fmaxf(m, __shfl_xor_sync(0xffffffffu, m, o));
    float e0 = expf(v0 - m), e1 = expf(v1 - m);
    float e2 = (lane < 16) ? expf(v2 - m) : 0.0f;
    float s = e0 + e1 + e2;
#pragma unroll
    for (int o = 16; o > 0; o >>= 1) s += __shfl_xor_sync(0xffffffffu, s, o);
    float inv = 1.0f / s;
    p[lane] = e0 * inv;
    p[lane + 32] = e1 * inv;
    if (lane < 16) p[lane + 64] = e2 * inv;
}

// =====================================================================
// deformable sampling: one warp per (token, head)
// lanes: half = lane>>4 selects x-tap (x0/x1), dp = lane&15 selects d-pair
// =====================================================================
__global__ void sample_kernel(const float* __restrict__ refpts) {
    int warp = threadIdx.x >> 5, lane = threadIdx.x & 31;
    int unit = blockIdx.x * 8 + warp;                // 81920 units
    int token = unit >> 3;
    int h = unit & 7;
    int b = token / LQQ;

    __shared__ float s_off[8][160];
    __shared__ float s_aw[8][80];
    __shared__ float s_ref[8][10];

    const float* offp = g_off + (size_t)token * 1280 + h * 160;
    for (int i = lane; i < 160; i += 32) s_off[warp][i] = offp[i];
    const float* awp = g_aw + (size_t)token * 640 + h * 80;
    for (int i = lane; i < 80; i += 32) s_aw[warp][i] = awp[i];
    const float* rp = refpts + (size_t)token * 10;
    if (lane < 10) s_ref[warp][lane] = rp[lane];
    __syncwarp();

    int half = lane >> 4, dp = lane & 15;
    float accx = 0.0f, accy = 0.0f;

#pragma unroll
    for (int l = 0; l < NLL; ++l) {
        const __nv_bfloat162* vb =
            (const __nv_bfloat162*)g_vperm + ((size_t)((b * NHH + h) * NLL + l) << 14);
        float rx = s_ref[warp][l * 2 + 0] * 32.0f - 0.5f;
        float ry = s_ref[warp][l * 2 + 1] * 32.0f - 0.5f;
#pragma unroll 4
        for (int p = 0; p < NPP; ++p) {
            int s = l * NPP + p;
            float px = rx + s_off[warp][s * 2 + 0];
            float py = ry + s_off[warp][s * 2 + 1];
            float a = s_aw[warp][s];
            float fx0 = floorf(px), fy0 = floorf(py);
            float fx = px - fx0, fy = py - fy0;
            int x0 = (int)fx0, y0 = (int)fy0;
            int xi = x0 + half;
            float wx = half ? fx : (1.0f - fx);
            bool vx = (xi >= 0) && (xi < WW);
            int xc = min(max(xi, 0), WW - 1);
#pragma unroll
            for (int t = 0; t < 2; ++t) {
                int yi = y0 + t;
                float wy = t ? fy : (1.0f - fy);
                bool vy = (yi >= 0) && (yi < HH);
                int yc = min(max(yi, 0), HH - 1);
                float wgt = (vx && vy) ? a * wx * wy : 0.0f;
                __nv_bfloat162 v = vb[((yc << 5) + xc) * 16 + dp];
                float2 vf = __bfloat1622float2(v);
                accx += wgt * vf.x;
                accy += wgt * vf.y;
            }
        }
    }
    accx += __shfl_xor_sync(0xffffffffu, accx, 16);
    accy += __shfl_xor_sync(0xffffffffu, accy, 16);
    if (half == 0) {
        __nv_bfloat162* op = (__nv_bfloat162*)g_samp + (size_t)token * 128 + h * 16 + dp;
        *op = __floats2bfloat162_rn(accx, accy);
    }
}

// =====================================================================
// launch
// =====================================================================
extern "C" void kernel_launch(void* const* d_in, const int* in_sizes, int n_in,
                              void* d_out, int out_size) {
    const float* x      = (const float*)d_in[0];
    const float* refpts = (const float*)d_in[1];
    const float* n3g = (const float*)d_in[4];
    const float* n3b = (const float*)d_in[5];
    const float* n4g = (const float*)d_in[6];
    const float* n4b = (const float*)d_in[7];
    const float* w_off  = (const float*)d_in[8];
    const float* b_off  = (const float*)d_in[9];
    const float* w_attn = (const float*)d_in[10];
    const float* b_attn = (const float*)d_in[11];
    const float* w_val  = (const float*)d_in[12];
    const float* b_val  = (const float*)d_in[13];
    const float* w_out  = (const float*)d_in[14];
    const float* b_out  = (const float*)d_in[15];
    const float* w_fc1  = (const float*)d_in[16];
    const float* b_fc1  = (const float*)d_in[17];
    const float* w_fc2  = (const float*)d_in[18];
    const float* b_fc2  = (const float*)d_in[19];
    float* outp = (float*)d_out;

    // device-global scratch addresses
    void *p_q, *p_hln, *p_samp, *p_mh, *p_val, *p_off, *p_aw, *p_x1;
    void *p_wv, *p_wo, *p_wa, *p_wou, *p_wf1, *p_wf2;
    cudaGetSymbolAddress(&p_q, g_q);
    cudaGetSymbolAddress(&p_hln, g_hln);
    cudaGetSymbolAddress(&p_samp, g_samp);
    cudaGetSymbolAddress(&p_mh, g_mh);
    cudaGetSymbolAddress(&p_val, g_val);
    cudaGetSymbolAddress(&p_off, g_off);
    cudaGetSymbolAddress(&p_aw, g_aw);
    cudaGetSymbolAddress(&p_x1, g_x1);
    cudaGetSymbolAddress(&p_wv, g_w_val);
    cudaGetSymbolAddress(&p_wo, g_w_off);
    cudaGetSymbolAddress(&p_wa, g_w_attn);
    cudaGetSymbolAddress(&p_wou, g_w_out);
    cudaGetSymbolAddress(&p_wf1, g_w_fc1);
    cudaGetSymbolAddress(&p_wf2, g_w_fc2);

    // 1. weights -> bf16
    convert_weights_kernel<<<4480, 256>>>(w_val, w_off, w_attn, w_out, w_fc1, w_fc2);

    // 2. q = LN(x)  (bf16)
    ln_kernel<<<MM / 8, 256>>>(x, n3g, n3b, (__nv_bfloat16*)p_q);

    // 3-5. three projections from q
    gemm_bf16_kernel<<<dim3(CC / 64, MM / 128), 256>>>(
        (const __nv_bfloat16*)p_q, (const __nv_bfloat16*)p_wv, b_val,
        nullptr, (float*)p_val, nullptr, MM, CC, CC, 0);
    gemm_bf16_kernel<<<dim3(1280 / 64, MM / 128), 256>>>(
        (const __nv_bfloat16*)p_q, (const __nv_bfloat16*)p_wo, b_off,
        nullptr, (float*)p_off, nullptr, MM, 1280, CC, 0);
    gemm_bf16_kernel<<<dim3(640 / 64, MM / 128), 256>>>(
        (const __nv_bfloat16*)p_q, (const __nv_bfloat16*)p_wa, b_attn,
        nullptr, (float*)p_aw, nullptr, MM, 640, CC, 0);

    // 6. value permute to [b,h,l,yx,d] bf16
    permute_val_kernel<<<(BD * NHH * NLL * HWW * HDD) / 256, 256>>>();

    // 7. softmax over 80
    softmax80_kernel<<<MM * NHH / 8, 256>>>();

    // 8. deformable bilinear sampling -> g_samp (bf16)
    sample_kernel<<<MM * NHH / 8, 256>>>(refpts);

    // 9. out-proj + residual(x) -> x1 (f32)
    gemm_bf16_kernel<<<dim3(CC / 64, MM / 128), 256>>>(
        (const __nv_bfloat16*)p_samp, (const __nv_bfloat16*)p_wou, b_out,
        x, (float*)p_x1, nullptr, MM, CC, CC, 0);

    // 10. h = LN(x1) (bf16)
    ln_kernel<<<MM / 8, 256>>>((const float*)p_x1, n4g, n4b, (__nv_bfloat16*)p_hln);

    // 11. fc1 + GELU -> mh (bf16)
    gemm_bf16_kernel<<<dim3(MLPH / 64, MM / 128), 256>>>(
        (const __nv_bfloat16*)p_hln, (const __nv_bfloat16*)p_wf1, b_fc1,
        nullptr, nullptr, (__nv_bfloat16*)p_mh, MM, MLPH, CC, 1);

    // 12. fc2 + residual(x1) -> d_out (f32)
    gemm_bf16_kernel<<<dim3(CC / 64, MM / 128), 256>>>(
        (const __nv_bfloat16*)p_mh, (const __nv_bfloat16*)p_wf2, b_fc2,
        (const float*)p_x1, outp, nullptr, MM, CC, MLPH, 0);
}